// round 14
// baseline (speedup 1.0000x reference)
#include <cuda_runtime.h>
#include <cstdint>
#include <cstddef>

#define S    512
#define TT   2048
#define NB   16
#define CLU  16          // CTAs per cluster (non-portable size)
#define CPC  32          // columns per CTA
#define NTHR 256         // 8 warps, 4 cols per warp
#define LN_EPS 1e-5f

typedef unsigned long long ull;

// per-buffer mbarrier: 16 src x 8 warps x 3 msgs x 8B
#define STEP_TX_BYTES 3072u

// ---------------- scratch (allocation-free rule: __device__ globals) ----------
__device__ float g_bufU[(size_t)NB * TT * S];   // 64MB
__device__ float g_bufH[(size_t)NB * TT * S];   // 64MB
__device__ float g_W01[(size_t)S * S];          // 1MB
__device__ float g_dummy[32];

// ---------------- PTX helpers -------------------------------------------------
__device__ __forceinline__ uint32_t smem_u32(const void* p) {
    return (uint32_t)__cvta_generic_to_shared(p);
}
__device__ __forceinline__ uint32_t mapa_shared(uint32_t addr, int rank) {
    uint32_t out;
    asm("mapa.shared::cluster.u32 %0, %1, %2;" : "=r"(out) : "r"(addr), "r"(rank));
    return out;
}
__device__ __forceinline__ void st_async_b64(uint32_t dst, ull v, uint32_t mbar) {
    asm volatile(
        "st.async.shared::cluster.mbarrier::complete_tx::bytes.b64 [%0], %1, [%2];"
        :: "r"(dst), "l"(v), "r"(mbar) : "memory");
}
__device__ __forceinline__ void mbar_init(uint32_t addr, uint32_t cnt) {
    asm volatile("mbarrier.init.shared.b64 [%0], %1;" :: "r"(addr), "r"(cnt) : "memory");
}
__device__ __forceinline__ void mbar_expect_tx(uint32_t addr, uint32_t bytes) {
    asm volatile("mbarrier.arrive.expect_tx.shared.b64 _, [%0], %1;"
                 :: "r"(addr), "r"(bytes) : "memory");
}
__device__ __forceinline__ void mbar_wait_parity(uint32_t addr, uint32_t phase) {
    uint32_t done = 0;
    while (!done) {
        asm volatile(
            "{\n\t.reg .pred p;\n\t"
            "mbarrier.try_wait.parity.acquire.cta.shared::cta.b64 p, [%1], %2, 0x989680;\n\t"
            "selp.b32 %0, 1, 0, p;\n\t}"
            : "=r"(done) : "r"(addr), "r"(phase) : "memory");
    }
}
__device__ __forceinline__ void cluster_barrier() {
    asm volatile("barrier.cluster.arrive.aligned;" ::: "memory");
    asm volatile("barrier.cluster.wait.aligned;"  ::: "memory");
}
__device__ __forceinline__ ull pk(float x, float y) {
    ull r; asm("mov.b64 %0, {%1, %2};" : "=l"(r) : "f"(x), "f"(y)); return r;
}
__device__ __forceinline__ float2 upk(ull v) {
    float2 r; asm("mov.b64 {%0, %1}, %2;" : "=f"(r.x), "=f"(r.y) : "l"(v)); return r;
}
__device__ __forceinline__ ull ffma2(ull a, ull b, ull c) {
    ull d; asm("fma.rn.f32x2 %0, %1, %2, %3;" : "=l"(d) : "l"(a), "l"(b), "l"(c)); return d;
}

// ---------------- scan kernel -------------------------------------------------
// grid = 256 CTAs = 16 clusters of 16, TWO CTAs PER SM (launch_bounds(256,2),
// ~80KB smem each). Cluster c = batch c; CTA rank owns 32 cols. When one CTA
// sleeps in its mbarrier TRYWAIT, the co-resident CTA (different batch)
// computes — the HW scheduler provides the latency hiding that R8/R13's
// manual dual-batch interleave paid 255-reg spills for. Simple R5-style
// single-batch loop: matmul -> butterfly -> lanes 0-15 st.async 4 z + 1
// partial to each rank -> parity wait -> redundant LN reduce -> LN+GELU ->
// h_sm. One __syncthreads per step.
extern __shared__ float sm[];

// sm floats [0..4): 2 mbarriers (16B), m = t&1
#define A_OFF   16
#define H_OFF   (A_OFF + CPC * S)          // h [512]
#define ZB_OFF  (H_OFF + S)                // zb [2][512]
#define PT_OFF  (ZB_OFF + 2 * S)           // part [2][128][2]
#define AB_OFF  (PT_OFF + 2 * 128 * 2)     // ab [512]
#define G_OFF   (AB_OFF + S)               // gamma [512]
#define B_OFF   (G_OFF + S)                // beta [512]
#define SM_FLTS (B_OFF + S)
static const size_t SCAN_SMEM = (size_t)SM_FLTS * sizeof(float);

__global__ void __cluster_dims__(CLU, 1, 1) __launch_bounds__(NTHR, 2)
scan_kernel(const float* __restrict__ Aw, const float* __restrict__ Kw,
            const float* __restrict__ ab, const float* __restrict__ gg,
            const float* __restrict__ bb, const float* __restrict__ U,
            float* __restrict__ HS)
{
    float* A_sm  = sm + A_OFF;             // [32][512]
    float* h_sm  = sm + H_OFF;             // [512]
    float* zb    = sm + ZB_OFF;            // [2][512]
    float* part  = sm + PT_OFF;            // [2][128][2]
    float* ab_sm = sm + AB_OFF;
    float* g_sm  = sm + G_OFF;
    float* b_sm  = sm + B_OFF;

    const uint32_t mb_u = smem_u32(sm);    // mbar[m] at +8m
    const int tid  = threadIdx.x;
    const int lane = tid & 31;
    const int w    = tid >> 5;             // warp 0..7
    const int batch = blockIdx.x >> 4;     // cluster id = batch
    const int rank  = blockIdx.x & 15;
    const int wcol  = rank * CPC + 4 * w;  // first global col of this warp

    if (tid < 2) {
        mbar_init(mb_u + tid * 8, 1);
        mbar_expect_tx(mb_u + tid * 8, STEP_TX_BYTES);
    }

    // A slice: A_sm[c][j] = Aw[j*S + rank*32 + c]
    for (int idx = tid; idx < CPC * S; idx += NTHR) {
        int j = idx >> 5, c = idx & 31;
        A_sm[c * S + j] = Aw[(size_t)j * S + rank * CPC + c];
    }
    for (int i = tid; i < S; i += NTHR) {
        h_sm[i] = 0.f; ab_sm[i] = ab[i]; g_sm[i] = gg[i]; b_sm[i] = bb[i];
    }

    // K packed: kp[c][r][p] = (K[k0+2p][wcol+c], K[k0+2p+1][wcol+c]), k0=4*lane+128*r
    ull kp[4][4][2];
#pragma unroll
    for (int c = 0; c < 4; c++)
#pragma unroll
        for (int r = 0; r < 4; r++) {
            int k0 = 4 * lane + 128 * r;
            kp[c][r][0] = pk(Kw[(size_t)(k0 + 0) * S + wcol + c],
                             Kw[(size_t)(k0 + 1) * S + wcol + c]);
            kp[c][r][1] = pk(Kw[(size_t)(k0 + 2) * S + wcol + c],
                             Kw[(size_t)(k0 + 3) * S + wcol + c]);
        }

    float2 hreg = make_float2(0.f, 0.f);

    // per-lane remote base (lane L -> rank L, L<16)
    const uint32_t rb = mapa_shared(mb_u, lane & 15);

    __syncthreads();
    cluster_barrier();   // mbarrier arming + A_sm/h_sm visible cluster-wide

    const float* Ub = U  + (size_t)batch * TT * S;
    float*       Hb = HS + (size_t)batch * TT * S;

    for (int t = 0; t < TT; t++) {
        const int m   = t & 1;
        const int par = (t >> 1) & 1;

        // u(t) and u(t-1): issued early, consumed after the matmul (hidden);
        // u(t-1) line is an L1 hit (read as u(t) last step)
        float4 uc = *(const float4*)&Ub[(size_t)t * S + wcol];
        float4 up = make_float4(0.f, 0.f, 0.f, 0.f);
        if (t > 0) up = *(const float4*)&Ub[(size_t)(t - 1) * S + wcol];

        ull hp[4][2];
#pragma unroll
        for (int r = 0; r < 4; r++) {
            ulonglong2 hv = *(const ulonglong2*)&h_sm[4 * lane + 128 * r];
            hp[r][0] = hv.x; hp[r][1] = hv.y;
        }

        ull accA[4], accK[4];
#pragma unroll
        for (int c = 0; c < 4; c++) { accA[c] = 0ull; accK[c] = 0ull; }
#pragma unroll
        for (int c = 0; c < 4; c++) {
            const float* Ac = A_sm + (size_t)(4 * w + c) * S;
#pragma unroll
            for (int r = 0; r < 4; r++) {
                ulonglong2 av = *(const ulonglong2*)&Ac[4 * lane + 128 * r];
                accA[c] = ffma2(av.x, hp[r][0], accA[c]);
                accA[c] = ffma2(av.y, hp[r][1], accA[c]);
                accK[c] = ffma2(kp[c][r][0], hp[r][0], accK[c]);
                accK[c] = ffma2(kp[c][r][1], hp[r][1], accK[c]);
            }
        }
        float z[4];
        {
            float2 a, k;
            a = upk(accA[0]); k = upk(accK[0]); z[0] = (a.x + a.y) + (k.x + k.y) * up.x;
            a = upk(accA[1]); k = upk(accK[1]); z[1] = (a.x + a.y) + (k.x + k.y) * up.y;
            a = upk(accA[2]); k = upk(accK[2]); z[2] = (a.x + a.y) + (k.x + k.y) * up.z;
            a = upk(accA[3]); k = upk(accK[3]); z[3] = (a.x + a.y) + (k.x + k.y) * up.w;
        }
#pragma unroll
        for (int off = 16; off > 0; off >>= 1) {
#pragma unroll
            for (int c = 0; c < 4; c++)
                z[c] += __shfl_xor_sync(0xffffffffu, z[c], off);
        }
        {
            float4 a4 = *(const float4*)&ab_sm[wcol];
            z[0] += a4.x + uc.x; z[1] += a4.y + uc.y;
            z[2] += a4.z + uc.z; z[3] += a4.w + uc.w;
        }
        float s1 = (z[0] + z[1]) + (z[2] + z[3]);
        float s2 = (z[0]*z[0] + z[1]*z[1]) + (z[2]*z[2] + z[3]*z[3]);

        // ---- lane L -> rank L (L<16): 2 z-pair msgs + 1 partial msg
        if (lane < 16) {
            const uint32_t mb = rb + (uint32_t)(m * 8);
            uint32_t zd = rb + (uint32_t)((ZB_OFF + m * S + wcol) * 4);
            st_async_b64(zd,     pk(z[0], z[1]), mb);
            st_async_b64(zd + 8, pk(z[2], z[3]), mb);
            st_async_b64(rb + (uint32_t)((PT_OFF + (m * 128 + rank * 8 + w) * 2) * 4),
                         pk(s1, s2), mb);
        }

        // ---- consume
        mbar_wait_parity(mb_u + m * 8, (uint32_t)par);
        if (tid == 0) mbar_expect_tx(mb_u + m * 8, STEP_TX_BYTES);  // re-arm t+2

        // 128 partial pairs -> LN sums (per-warp redundant, 4 pairs/lane)
        const float* pt = part + m * 256;
        float4 p0 = *(const float4*)&pt[8 * lane];
        float4 p1 = *(const float4*)&pt[8 * lane + 4];
        float t1 = (p0.x + p0.z) + (p1.x + p1.z);
        float t2 = (p0.y + p0.w) + (p1.y + p1.w);
#pragma unroll
        for (int off = 16; off > 0; off >>= 1) {
            t1 += __shfl_xor_sync(0xffffffffu, t1, off);
            t2 += __shfl_xor_sync(0xffffffffu, t2, off);
        }
        const float mu   = t1 * (1.f / S);
        const float rinv = rsqrtf(t2 * (1.f / S) - mu * mu + LN_EPS);

        float2 zv = *(const float2*)&zb[m * S + 2 * tid];
        float2 g2 = *(const float2*)&g_sm[2 * tid];
        float2 b2 = *(const float2*)&b_sm[2 * tid];
        float zn0 = (zv.x - mu) * rinv * g2.x + b2.x;
        float zn1 = (zv.y - mu) * rinv * g2.y + b2.y;
        hreg.x += 0.5f * zn0 * (1.f + erff(zn0 * 0.70710678118654752f));
        hreg.y += 0.5f * zn1 * (1.f + erff(zn1 * 0.70710678118654752f));
        *(float2*)&h_sm[2 * tid] = hreg;
        // threads [16*rank, 16*rank+16) cover this CTA's 32-col slice
        if ((tid >> 4) == rank)
            *(float2*)&Hb[(size_t)t * S + 2 * tid] = hreg;
        __syncthreads();   // h_sm complete before next step's matmul
    }
    cluster_barrier();     // no CTA exits while peers may still touch its smem
}

// ---------------- dummy (shifts ncu -s 5 onto the 2nd scan) -------------------
__global__ void dummy_kernel() {
    if (threadIdx.x < 32) g_dummy[threadIdx.x] = 0.f;
}

// ---------------- fp32 tiled GEMM:  C[M,N] = A[M,K] * B[K,N]  (all row-major) --
#define BM 128
#define BN 128
#define BK 16

__global__ void __launch_bounds__(256, 2)
gemm_kernel(const float* __restrict__ A, const float* __restrict__ B,
            float* __restrict__ C, int M, int N, int Kd)
{
    __shared__ float As[BK][BM];
    __shared__ float Bs[BK][BN];

    const int t  = threadIdx.x;
    const int tx = t & 15, ty = t >> 4;
    const int m0 = blockIdx.y * BM, n0 = blockIdx.x * BN;

    float acc[8][8] = {};

    for (int k0 = 0; k0 < Kd; k0 += BK) {
#pragma unroll
        for (int q = 0; q < 2; q++) {
            int idx = t + q * 256;
            int arow = idx >> 2, kc = (idx & 3) * 4;
            float4 v = *(const float4*)&A[(size_t)(m0 + arow) * Kd + k0 + kc];
            As[kc + 0][arow] = v.x; As[kc + 1][arow] = v.y;
            As[kc + 2][arow] = v.z; As[kc + 3][arow] = v.w;
        }
#pragma unroll
        for (int q = 0; q < 2; q++) {
            int idx = t + q * 256;
            int brow = idx >> 5, bc = (idx & 31) * 4;
            *(float4*)&Bs[brow][bc] = *(const float4*)&B[(size_t)(k0 + brow) * N + n0 + bc];
        }
        __syncthreads();
#pragma unroll
        for (int kk = 0; kk < BK; kk++) {
            float4 a0 = *(const float4*)&As[kk][ty * 4];
            float4 a1 = *(const float4*)&As[kk][ty * 4 + 64];
            float4 b0 = *(const float4*)&Bs[kk][tx * 4];
            float4 b1 = *(const float4*)&Bs[kk][tx * 4 + 64];
            float av[8] = {a0.x, a0.y, a0.z, a0.w, a1.x, a1.y, a1.z, a1.w};
            float bv[8] = {b0.x, b0.y, b0.z, b0.w, b1.x, b1.y, b1.z, b1.w};
#pragma unroll
            for (int i = 0; i < 8; i++)
#pragma unroll
                for (int j = 0; j < 8; j++)
                    acc[i][j] += av[i] * bv[j];
        }
        __syncthreads();
    }

#pragma unroll
    for (int i = 0; i < 8; i++) {
        int row = m0 + ((i < 4) ? (ty * 4 + i) : (64 + ty * 4 + (i - 4)));
        float4 c0 = make_float4(acc[i][0], acc[i][1], acc[i][2], acc[i][3]);
        float4 c1 = make_float4(acc[i][4], acc[i][5], acc[i][6], acc[i][7]);
        *(float4*)&C[(size_t)row * N + n0 + tx * 4]      = c0;
        *(float4*)&C[(size_t)row * N + n0 + 64 + tx * 4] = c1;
    }
}

// ---------------- launch ------------------------------------------------------
extern "C" void kernel_launch(void* const* d_in, const int* in_sizes, int n_in,
                              void* d_out, int out_size)
{
    (void)in_sizes; (void)n_in; (void)out_size;
    const float* x   = (const float*)d_in[0];
    const float* A0  = (const float*)d_in[1];
    const float* B0  = (const float*)d_in[2];
    const float* C0  = (const float*)d_in[3];
    const float* K0  = (const float*)d_in[4];
    const float* ab0 = (const float*)d_in[5];
    const float* g0  = (const float*)d_in[6];
    const float* bt0 = (const float*)d_in[7];
    const float* A1  = (const float*)d_in[8];
    const float* B1  = (const float*)d_in[9];
    const float* C1  = (const float*)d_in[10];
    const float* K1  = (const float*)d_in[11];
    const float* ab1 = (const float*)d_in[12];
    const float* g1  = (const float*)d_in[13];
    const float* bt1 = (const float*)d_in[14];
    float* out = (float*)d_out;

    float *U, *H, *W01;
    cudaGetSymbolAddress((void**)&U,   g_bufU);
    cudaGetSymbolAddress((void**)&H,   g_bufH);
    cudaGetSymbolAddress((void**)&W01, g_W01);

    cudaFuncSetAttribute(scan_kernel, cudaFuncAttributeMaxDynamicSharedMemorySize,
                         (int)SCAN_SMEM);
    cudaFuncSetAttribute(scan_kernel, cudaFuncAttributeNonPortableClusterSizeAllowed, 1);

    const int M = NB * TT;                        // 32768
    dim3 gBig(S / BN, M / BM);                    // (4, 256)
    dim3 gSmall(S / BN, S / BM);                  // (4, 4)
    const int SCAN_GRID = NB * CLU;               // 256 CTAs = 16 clusters of 16

    // [0] dummy: shifts ncu -s 5 -c 1 onto the 2nd scan kernel
    dummy_kernel<<<1, 32>>>();
    // [1] W01 = C0 @ B1   (fuse: (hs@C0)@B1 = hs@(C0@B1))
    gemm_kernel<<<gSmall, 256>>>(C0, B1, W01, S, S, S);
    // [2] U = x @ B0
    gemm_kernel<<<gBig, 256>>>(x, B0, U, M, S, S);
    // [3] layer 0 scan -> H
    scan_kernel<<<SCAN_GRID, NTHR, SCAN_SMEM>>>(A0, K0, ab0, g0, bt0, U, H);
    // [4] U = H @ W01
    gemm_kernel<<<gBig, 256>>>(H, W01, U, M, S, S);
    // [5] layer 1 scan -> H   <-- profiled
    scan_kernel<<<SCAN_GRID, NTHR, SCAN_SMEM>>>(A1, K1, ab1, g1, bt1, U, H);
    // [6] out = H @ C1
    gemm_kernel<<<gBig, 256>>>(H, C1, out, M, S, S);
}

// round 15
// speedup vs baseline: 1.0899x; 1.0899x over previous
#include <cuda_runtime.h>
#include <cstdint>
#include <cstddef>

#define S    512
#define TT   2048
#define NB   16
#define CLU  8           // CTAs per cluster
#define CPC  64          // columns per CTA
#define NTHR 512         // 16 warps, 4 cols per warp
#define LN_EPS 1e-5f

typedef unsigned long long ull;

// per (batch,buffer) mbarrier: 8 src x 16 warps x 3 msgs x 8B
#define STEP_TX_BYTES 3072u

// ---------------- scratch (allocation-free rule: __device__ globals) ----------
__device__ float g_bufU[(size_t)NB * TT * S];   // 64MB
__device__ float g_bufH[(size_t)NB * TT * S];   // 64MB
__device__ float g_W01[(size_t)S * S];          // 1MB
__device__ float g_dummy[32];

// ---------------- PTX helpers -------------------------------------------------
__device__ __forceinline__ uint32_t smem_u32(const void* p) {
    return (uint32_t)__cvta_generic_to_shared(p);
}
__device__ __forceinline__ uint32_t mapa_shared(uint32_t addr, int rank) {
    uint32_t out;
    asm("mapa.shared::cluster.u32 %0, %1, %2;" : "=r"(out) : "r"(addr), "r"(rank));
    return out;
}
__device__ __forceinline__ void st_async_b64(uint32_t dst, ull v, uint32_t mbar) {
    asm volatile(
        "st.async.shared::cluster.mbarrier::complete_tx::bytes.b64 [%0], %1, [%2];"
        :: "r"(dst), "l"(v), "r"(mbar) : "memory");
}
__device__ __forceinline__ void mbar_init(uint32_t addr, uint32_t cnt) {
    asm volatile("mbarrier.init.shared.b64 [%0], %1;" :: "r"(addr), "r"(cnt) : "memory");
}
__device__ __forceinline__ void mbar_expect_tx(uint32_t addr, uint32_t bytes) {
    asm volatile("mbarrier.arrive.expect_tx.shared.b64 _, [%0], %1;"
                 :: "r"(addr), "r"(bytes) : "memory");
}
__device__ __forceinline__ void mbar_wait_parity(uint32_t addr, uint32_t phase) {
    uint32_t done = 0;
    while (!done) {
        asm volatile(
            "{\n\t.reg .pred p;\n\t"
            "mbarrier.try_wait.parity.acquire.cta.shared::cta.b64 p, [%1], %2, 0x989680;\n\t"
            "selp.b32 %0, 1, 0, p;\n\t}"
            : "=r"(done) : "r"(addr), "r"(phase) : "memory");
    }
}
__device__ __forceinline__ void cluster_barrier() {
    asm volatile("barrier.cluster.arrive.aligned;" ::: "memory");
    asm volatile("barrier.cluster.wait.aligned;"  ::: "memory");
}
__device__ __forceinline__ ull pk(float x, float y) {
    ull r; asm("mov.b64 %0, {%1, %2};" : "=l"(r) : "f"(x), "f"(y)); return r;
}
__device__ __forceinline__ float2 upk(ull v) {
    float2 r; asm("mov.b64 {%0, %1}, %2;" : "=f"(r.x), "=f"(r.y) : "l"(v)); return r;
}
__device__ __forceinline__ ull ffma2(ull a, ull b, ull c) {
    ull d; asm("fma.rn.f32x2 %0, %1, %2, %3;" : "=l"(d) : "l"(a), "l"(b), "l"(c)); return d;
}

// ---------------- scan kernel -------------------------------------------------
// grid = 64 CTAs = 8 clusters of 8. Cluster c runs batches 2c/2c+1
// INTERLEAVED: each batch's exchange+wait hides under the other batch's
// compute (per-SM 2x, R8/R13-proven). 512 threads = 16 warps x 4 cols:
// kp[4][4][2] = 64 regs; total live ~120 <= 128-reg cap -> NO SPILLS (fix
// for R13's 255-reg spill). R5 protocol: matmul -> butterfly -> lanes 0-7
// st.async 2 z-pair msgs + 1 per-warp LN partial to each rank -> parity
// wait -> 128-pair redundant LN reduce -> 1 col/thread LN+GELU -> h_sm.
extern __shared__ float sm[];

// sm floats [0..8): 4 mbarriers (32B), q = b*2 + (t&1)
#define A_OFF   16
#define H_OFF   (A_OFF + CPC * S)          // h [2][512]
#define ZB_OFF  (H_OFF + 2 * S)            // zb [4][512]
#define PT_OFF  (ZB_OFF + 4 * S)           // part [4][128][2]
#define AB_OFF  (PT_OFF + 4 * 128 * 2)     // ab [512]
#define SM_FLTS (AB_OFF + S)
static const size_t SCAN_SMEM = (size_t)SM_FLTS * sizeof(float);

__global__ void __cluster_dims__(CLU, 1, 1) __launch_bounds__(NTHR, 1)
scan_kernel(const float* __restrict__ Aw, const float* __restrict__ Kw,
            const float* __restrict__ ab, const float* __restrict__ gg,
            const float* __restrict__ bb, const float* __restrict__ U,
            float* __restrict__ HS)
{
    float* A_sm  = sm + A_OFF;             // [64][512]
    float* h_sm  = sm + H_OFF;             // [2][512]
    float* zb    = sm + ZB_OFF;            // [4][512]
    float* part  = sm + PT_OFF;            // [4][128][2]
    float* ab_sm = sm + AB_OFF;            // [512]

    const uint32_t mb_u = smem_u32(sm);    // mbar[q] at +8q
    const int tid  = threadIdx.x;
    const int lane = tid & 31;
    const int w    = tid >> 5;             // warp 0..15
    const int cid  = blockIdx.x >> 3;      // cluster id: batches 2cid, 2cid+1
    const int rank = blockIdx.x & 7;
    const int wcol = rank * CPC + 4 * w;   // first global col of this warp

    if (tid < 4) {
        mbar_init(mb_u + tid * 8, 1);
        mbar_expect_tx(mb_u + tid * 8, STEP_TX_BYTES);
    }

    // A slice: A_sm[c][j] = Aw[j*S + rank*64 + c]
    for (int idx = tid; idx < CPC * S; idx += NTHR) {
        int j = idx >> 6, c = idx & 63;
        A_sm[c * S + j] = Aw[(size_t)j * S + rank * CPC + c];
    }
    for (int i = tid; i < 2 * S; i += NTHR) h_sm[i] = 0.f;
    for (int i = tid; i < S; i += NTHR) ab_sm[i] = ab[i];

    // K packed: kp[c][r][p] = (K[k0+2p][wcol+c], K[k0+2p+1][wcol+c]), k0=4*lane+128*r
    ull kp[4][4][2];
#pragma unroll
    for (int c = 0; c < 4; c++)
#pragma unroll
        for (int r = 0; r < 4; r++) {
            int k0 = 4 * lane + 128 * r;
            kp[c][r][0] = pk(Kw[(size_t)(k0 + 0) * S + wcol + c],
                             Kw[(size_t)(k0 + 1) * S + wcol + c]);
            kp[c][r][1] = pk(Kw[(size_t)(k0 + 2) * S + wcol + c],
                             Kw[(size_t)(k0 + 3) * S + wcol + c]);
        }

    const float gv = gg[tid];              // this thread's single column
    const float bv = bb[tid];
    float hreg0 = 0.f, hreg1 = 0.f;

    // per-lane remote base (lane L -> rank L)
    const uint32_t rb = mapa_shared(mb_u, lane & 7);

    __syncthreads();
    cluster_barrier();   // mbarrier arming + A_sm/h_sm visible cluster-wide

    const float* Ub0 = U + (size_t)(2 * cid + 0) * TT * S;
    const float* Ub1 = U + (size_t)(2 * cid + 1) * TT * S;
    float* Hb0 = HS + (size_t)(2 * cid + 0) * TT * S;
    float* Hb1 = HS + (size_t)(2 * cid + 1) * TT * S;

    // ---- compute z(b,t), send to all 8 ranks (3 msgs per lane<8)
    auto compute_send = [&](int b, int t, const float* Ubb) {
        const int q = b * 2 + (t & 1);

        // u(t): fresh; u(t-1): L1 hit (loaded as u(t) two phases ago)
        float4 uc = *(const float4*)&Ubb[(size_t)t * S + wcol];
        float4 up = make_float4(0.f, 0.f, 0.f, 0.f);
        if (t > 0) up = *(const float4*)&Ubb[(size_t)(t - 1) * S + wcol];

        ull hp[4][2];
#pragma unroll
        for (int r = 0; r < 4; r++) {
            ulonglong2 hv = *(const ulonglong2*)&h_sm[b * S + 4 * lane + 128 * r];
            hp[r][0] = hv.x; hp[r][1] = hv.y;
        }

        ull accA[4], accK[4];
#pragma unroll
        for (int c = 0; c < 4; c++) { accA[c] = 0ull; accK[c] = 0ull; }
#pragma unroll
        for (int c = 0; c < 4; c++) {
            const float* Ac = A_sm + (size_t)(4 * w + c) * S;
#pragma unroll
            for (int r = 0; r < 4; r++) {
                ulonglong2 av = *(const ulonglong2*)&Ac[4 * lane + 128 * r];
                accA[c] = ffma2(av.x, hp[r][0], accA[c]);
                accA[c] = ffma2(av.y, hp[r][1], accA[c]);
                accK[c] = ffma2(kp[c][r][0], hp[r][0], accK[c]);
                accK[c] = ffma2(kp[c][r][1], hp[r][1], accK[c]);
            }
        }
        float z[4];
        {
            float2 a, k;
            a = upk(accA[0]); k = upk(accK[0]); z[0] = (a.x + a.y) + (k.x + k.y) * up.x;
            a = upk(accA[1]); k = upk(accK[1]); z[1] = (a.x + a.y) + (k.x + k.y) * up.y;
            a = upk(accA[2]); k = upk(accK[2]); z[2] = (a.x + a.y) + (k.x + k.y) * up.z;
            a = upk(accA[3]); k = upk(accK[3]); z[3] = (a.x + a.y) + (k.x + k.y) * up.w;
        }
#pragma unroll
        for (int off = 16; off > 0; off >>= 1) {
#pragma unroll
            for (int c = 0; c < 4; c++)
                z[c] += __shfl_xor_sync(0xffffffffu, z[c], off);
        }
        {
            float4 a4 = *(const float4*)&ab_sm[wcol];
            z[0] += a4.x + uc.x; z[1] += a4.y + uc.y;
            z[2] += a4.z + uc.z; z[3] += a4.w + uc.w;
        }
        float s1 = (z[0] + z[1]) + (z[2] + z[3]);
        float s2 = (z[0]*z[0] + z[1]*z[1]) + (z[2]*z[2] + z[3]*z[3]);

        if (lane < 8) {
            const uint32_t mb = rb + (uint32_t)(q * 8);
            uint32_t zd = rb + (uint32_t)((ZB_OFF + q * S + wcol) * 4);
            st_async_b64(zd,     pk(z[0], z[1]), mb);
            st_async_b64(zd + 8, pk(z[2], z[3]), mb);
            st_async_b64(rb + (uint32_t)((PT_OFF + (q * 128 + rank * 16 + w) * 2) * 4),
                         pk(s1, s2), mb);
        }
    };

    // ---- wait for z(b,t), LN+GELU (1 col/thread), update h_sm[b]
    auto consume = [&](int b, int t, float& hr, float* Hbb) {
        const int q = b * 2 + (t & 1);
        const uint32_t mb = mb_u + (uint32_t)(q * 8);
        mbar_wait_parity(mb, (uint32_t)((t >> 1) & 1));
        if (tid == 0) mbar_expect_tx(mb, STEP_TX_BYTES);   // re-arm for t+2

        // 128 partial pairs -> LN sums (per-warp redundant, 4 pairs/lane)
        const float* pt = part + q * 256;
        float4 p0 = *(const float4*)&pt[8 * lane];
        float4 p1 = *(const float4*)&pt[8 * lane + 4];
        float t1 = (p0.x + p0.z) + (p1.x + p1.z);
        float t2 = (p0.y + p0.w) + (p1.y + p1.w);
#pragma unroll
        for (int off = 16; off > 0; off >>= 1) {
            t1 += __shfl_xor_sync(0xffffffffu, t1, off);
            t2 += __shfl_xor_sync(0xffffffffu, t2, off);
        }
        const float mu   = t1 * (1.f / S);
        const float rinv = rsqrtf(t2 * (1.f / S) - mu * mu + LN_EPS);

        float zn = (zb[q * S + tid] - mu) * rinv * gv + bv;
        hr += 0.5f * zn * (1.f + erff(zn * 0.70710678118654752f));
        h_sm[b * S + tid] = hr;
        // threads [64*rank, 64*rank+64) cover this CTA's column slice
        if ((tid >> 6) == rank)
            Hbb[(size_t)t * S + tid] = hr;
        __syncthreads();   // h_sm[b] complete before batch b's next matmul
    };

    // prologue: produce step 0 for both batches
    compute_send(0, 0, Ub0);
    compute_send(1, 0, Ub1);

    for (int t = 0; t < TT; t++) {
        consume(0, t, hreg0, Hb0);
        if (t + 1 < TT) compute_send(0, t + 1, Ub0);   // b0 exchange hides under b1
        consume(1, t, hreg1, Hb1);
        if (t + 1 < TT) compute_send(1, t + 1, Ub1);   // b1 exchange hides under b0
    }
    cluster_barrier();     // no CTA exits while peers may still touch its smem
}

// ---------------- dummy (shifts ncu -s 5 onto the 2nd scan) -------------------
__global__ void dummy_kernel() {
    if (threadIdx.x < 32) g_dummy[threadIdx.x] = 0.f;
}

// ---------------- fp32 tiled GEMM:  C[M,N] = A[M,K] * B[K,N]  (all row-major) --
#define BM 128
#define BN 128
#define BK 16

__global__ void __launch_bounds__(256, 2)
gemm_kernel(const float* __restrict__ A, const float* __restrict__ B,
            float* __restrict__ C, int M, int N, int Kd)
{
    __shared__ float As[BK][BM];
    __shared__ float Bs[BK][BN];

    const int t  = threadIdx.x;
    const int tx = t & 15, ty = t >> 4;
    const int m0 = blockIdx.y * BM, n0 = blockIdx.x * BN;

    float acc[8][8] = {};

    for (int k0 = 0; k0 < Kd; k0 += BK) {
#pragma unroll
        for (int q = 0; q < 2; q++) {
            int idx = t + q * 256;
            int arow = idx >> 2, kc = (idx & 3) * 4;
            float4 v = *(const float4*)&A[(size_t)(m0 + arow) * Kd + k0 + kc];
            As[kc + 0][arow] = v.x; As[kc + 1][arow] = v.y;
            As[kc + 2][arow] = v.z; As[kc + 3][arow] = v.w;
        }
#pragma unroll
        for (int q = 0; q < 2; q++) {
            int idx = t + q * 256;
            int brow = idx >> 5, bc = (idx & 31) * 4;
            *(float4*)&Bs[brow][bc] = *(const float4*)&B[(size_t)(k0 + brow) * N + n0 + bc];
        }
        __syncthreads();
#pragma unroll
        for (int kk = 0; kk < BK; kk++) {
            float4 a0 = *(const float4*)&As[kk][ty * 4];
            float4 a1 = *(const float4*)&As[kk][ty * 4 + 64];
            float4 b0 = *(const float4*)&Bs[kk][tx * 4];
            float4 b1 = *(const float4*)&Bs[kk][tx * 4 + 64];
            float av[8] = {a0.x, a0.y, a0.z, a0.w, a1.x, a1.y, a1.z, a1.w};
            float bv[8] = {b0.x, b0.y, b0.z, b0.w, b1.x, b1.y, b1.z, b1.w};
#pragma unroll
            for (int i = 0; i < 8; i++)
#pragma unroll
                for (int j = 0; j < 8; j++)
                    acc[i][j] += av[i] * bv[j];
        }
        __syncthreads();
    }

#pragma unroll
    for (int i = 0; i < 8; i++) {
        int row = m0 + ((i < 4) ? (ty * 4 + i) : (64 + ty * 4 + (i - 4)));
        float4 c0 = make_float4(acc[i][0], acc[i][1], acc[i][2], acc[i][3]);
        float4 c1 = make_float4(acc[i][4], acc[i][5], acc[i][6], acc[i][7]);
        *(float4*)&C[(size_t)row * N + n0 + tx * 4]      = c0;
        *(float4*)&C[(size_t)row * N + n0 + 64 + tx * 4] = c1;
    }
}

// ---------------- launch ------------------------------------------------------
extern "C" void kernel_launch(void* const* d_in, const int* in_sizes, int n_in,
                              void* d_out, int out_size)
{
    (void)in_sizes; (void)n_in; (void)out_size;
    const float* x   = (const float*)d_in[0];
    const float* A0  = (const float*)d_in[1];
    const float* B0  = (const float*)d_in[2];
    const float* C0  = (const float*)d_in[3];
    const float* K0  = (const float*)d_in[4];
    const float* ab0 = (const float*)d_in[5];
    const float* g0  = (const float*)d_in[6];
    const float* bt0 = (const float*)d_in[7];
    const float* A1  = (const float*)d_in[8];
    const float* B1  = (const float*)d_in[9];
    const float* C1  = (const float*)d_in[10];
    const float* K1  = (const float*)d_in[11];
    const float* ab1 = (const float*)d_in[12];
    const float* g1  = (const float*)d_in[13];
    const float* bt1 = (const float*)d_in[14];
    float* out = (float*)d_out;

    float *U, *H, *W01;
    cudaGetSymbolAddress((void**)&U,   g_bufU);
    cudaGetSymbolAddress((void**)&H,   g_bufH);
    cudaGetSymbolAddress((void**)&W01, g_W01);

    cudaFuncSetAttribute(scan_kernel, cudaFuncAttributeMaxDynamicSharedMemorySize,
                         (int)SCAN_SMEM);

    const int M = NB * TT;                        // 32768
    dim3 gBig(S / BN, M / BM);                    // (4, 256)
    dim3 gSmall(S / BN, S / BM);                  // (4, 4)
    const int SCAN_GRID = (NB / 2) * CLU;         // 64 CTAs = 8 clusters of 8

    // [0] dummy: shifts ncu -s 5 -c 1 onto the 2nd scan kernel
    dummy_kernel<<<1, 32>>>();
    // [1] W01 = C0 @ B1   (fuse: (hs@C0)@B1 = hs@(C0@B1))
    gemm_kernel<<<gSmall, 256>>>(C0, B1, W01, S, S, S);
    // [2] U = x @ B0
    gemm_kernel<<<gBig, 256>>>(x, B0, U, M, S, S);
    // [3] layer 0 scan -> H
    scan_kernel<<<SCAN_GRID, NTHR, SCAN_SMEM>>>(A0, K0, ab0, g0, bt0, U, H);
    // [4] U = H @ W01
    gemm_kernel<<<gBig, 256>>>(H, W01, U, M, S, S);
    // [5] layer 1 scan -> H   <-- profiled
    scan_kernel<<<SCAN_GRID, NTHR, SCAN_SMEM>>>(A1, K1, ab1, g1, bt1, U, H);
    // [6] out = H @ C1
    gemm_kernel<<<gBig, 256>>>(H, C1, out, M, S, S);
}

// round 16
// speedup vs baseline: 1.2464x; 1.1435x over previous
#include <cuda_runtime.h>
#include <cstdint>
#include <cstddef>

#define S    512
#define TT   2048
#define NB   16
#define CLU  8
#define CPC  64          // columns per CTA
#define NTHR 256         // 8 warps, 8 cols per warp
#define LN_EPS 1e-5f

typedef unsigned long long ull;

// Per-step inbound bytes per CTA: z 8CTA*8warp*4*8B = 2048, part 8*8*8B = 512
#define STEP_TX_BYTES 2560u

// ---------------- scratch (allocation-free rule: __device__ globals) ----------
__device__ float g_bufU[(size_t)NB * TT * S];   // 64MB
__device__ float g_bufH[(size_t)NB * TT * S];   // 64MB
__device__ float g_W01[(size_t)S * S];          // 1MB

// ---------------- PTX helpers -------------------------------------------------
__device__ __forceinline__ uint32_t smem_u32(const void* p) {
    return (uint32_t)__cvta_generic_to_shared(p);
}
__device__ __forceinline__ uint32_t mapa_shared(uint32_t addr, int rank) {
    uint32_t out;
    asm("mapa.shared::cluster.u32 %0, %1, %2;" : "=r"(out) : "r"(addr), "r"(rank));
    return out;
}
// st.async: data + tx-completion delivered to the REMOTE CTA's mbarrier.
__device__ __forceinline__ void st_async_b64(uint32_t dst, ull v, uint32_t mbar) {
    asm volatile(
        "st.async.shared::cluster.mbarrier::complete_tx::bytes.b64 [%0], %1, [%2];"
        :: "r"(dst), "l"(v), "r"(mbar) : "memory");
}
__device__ __forceinline__ void mbar_init(uint32_t addr, uint32_t cnt) {
    asm volatile("mbarrier.init.shared.b64 [%0], %1;" :: "r"(addr), "r"(cnt) : "memory");
}
__device__ __forceinline__ void mbar_expect_tx(uint32_t addr, uint32_t bytes) {
    asm volatile("mbarrier.arrive.expect_tx.shared.b64 _, [%0], %1;"
                 :: "r"(addr), "r"(bytes) : "memory");
}
__device__ __forceinline__ void mbar_wait_parity(uint32_t addr, uint32_t phase) {
    uint32_t done = 0;
    while (!done) {
        asm volatile(
            "{\n\t.reg .pred p;\n\t"
            "mbarrier.try_wait.parity.acquire.cta.shared::cta.b64 p, [%1], %2, 0x989680;\n\t"
            "selp.b32 %0, 1, 0, p;\n\t}"
            : "=r"(done) : "r"(addr), "r"(phase) : "memory");
    }
}
__device__ __forceinline__ void cluster_barrier() {
    asm volatile("barrier.cluster.arrive.aligned;" ::: "memory");
    asm volatile("barrier.cluster.wait.aligned;"  ::: "memory");
}
__device__ __forceinline__ ull pk(float x, float y) {
    ull r; asm("mov.b64 %0, {%1, %2};" : "=l"(r) : "f"(x), "f"(y)); return r;
}
__device__ __forceinline__ float2 upk(ull v) {
    float2 r; asm("mov.b64 {%0, %1}, %2;" : "=f"(r.x), "=f"(r.y) : "l"(v)); return r;
}
__device__ __forceinline__ ull ffma2(ull a, ull b, ull c) {
    ull d; asm("fma.rn.f32x2 %0, %1, %2, %3;" : "=l"(d) : "l"(a), "l"(b), "l"(c)); return d;
}

// ---------------- scan kernel (VERBATIM R5 — best measured: 13,025us) ---------
// grid = 128 CTAs = 16 clusters of 8. Cluster c = batch c.
// Per step: FFMA2 matmul -> butterfly reduce -> lanes 0-7 st.async packed z +
// LN partials to every rank (tx-counted on the remote mbarrier) -> local
// parity wait (acquire.cta) -> tid0 re-arms expect_tx for t+2 -> per-warp
// redundant LN reduce -> LN+GELU; h in regs, mirrored in SMEM. 1 sync/step.
extern __shared__ float sm[];

#define A_OFF   16
#define H_OFF   (A_OFF + CPC * S)          // 16 + 32768
#define ZB_OFF  (H_OFF + S)                // + 512
#define P_OFF   (ZB_OFF + 2 * S)           // + 1024
#define SM_FLTS (P_OFF + 2 * 64 * 2)       // + 256
static const size_t SCAN_SMEM = (size_t)SM_FLTS * sizeof(float);

__global__ void __cluster_dims__(CLU, 1, 1) __launch_bounds__(NTHR, 1)
scan_kernel(const float* __restrict__ Aw, const float* __restrict__ Kw,
            const float* __restrict__ ab, const float* __restrict__ gg,
            const float* __restrict__ bb, const float* __restrict__ U,
            float* __restrict__ HS)
{
    float* A_sm = sm + A_OFF;              // [64][512]
    float* h_sm = sm + H_OFF;              // [512]
    float* zb   = sm + ZB_OFF;             // [2][512]
    float* part = sm + P_OFF;              // [2][64][2]

    const uint32_t mbar_u = smem_u32(sm);  // mbar[0] at +0, mbar[1] at +8
    const int tid  = threadIdx.x;
    const int lane = tid & 31;
    const int w    = tid >> 5;             // warp 0..7
    const int batch = blockIdx.x / CLU;
    const int rank  = blockIdx.x % CLU;
    const int colbase = rank * CPC;
    const int wcol = colbase + 8 * w;      // first global col of this warp

    if (tid == 0) {
        mbar_init(mbar_u, 1);
        mbar_init(mbar_u + 8, 1);
        mbar_expect_tx(mbar_u,     STEP_TX_BYTES);
        mbar_expect_tx(mbar_u + 8, STEP_TX_BYTES);
    }

    // A slice: A_sm[c][j] = Aw[j*S + colbase + c]
    for (int idx = tid; idx < CPC * S; idx += NTHR) {
        int j = idx >> 6, c = idx & 63;
        A_sm[c * S + j] = Aw[(size_t)j * S + colbase + c];
    }
    for (int i = tid; i < S; i += NTHR) h_sm[i] = 0.f;

    // K packed: kp[c][r][p] = (K[k0+2p][wcol+c], K[k0+2p+1][wcol+c]), k0=4*lane+128*r
    ull kp[8][4][2];
#pragma unroll
    for (int c = 0; c < 8; c++)
#pragma unroll
        for (int r = 0; r < 4; r++) {
            int k0 = 4 * lane + 128 * r;
            kp[c][r][0] = pk(Kw[(size_t)(k0 + 0) * S + wcol + c],
                             Kw[(size_t)(k0 + 1) * S + wcol + c]);
            kp[c][r][1] = pk(Kw[(size_t)(k0 + 2) * S + wcol + c],
                             Kw[(size_t)(k0 + 3) * S + wcol + c]);
        }
    float abv[8];
#pragma unroll
    for (int c = 0; c < 8; c++) abv[c] = ab[wcol + c];

    const float2 g2 = *(const float2*)&gg[2 * tid];
    const float2 b2 = *(const float2*)&bb[2 * tid];
    float2 hreg = make_float2(0.f, 0.f);

    // per-lane remote addresses (lane L -> rank L)
    const int rr = lane & 7;
    const uint32_t zdst = mapa_shared(smem_u32(zb), rr);
    const uint32_t pdst = mapa_shared(smem_u32(part), rr);
    const uint32_t mdst = mapa_shared(mbar_u, rr);

    __syncthreads();
    cluster_barrier();   // mbarrier init + initial expects visible before stores

    const float* Ub = U  + (size_t)batch * TT * S;
    float*       Hb = HS + (size_t)batch * TT * S;

    float4 un0 = *(const float4*)&Ub[wcol];
    float4 un1 = *(const float4*)&Ub[wcol + 4];
    float4 up0 = make_float4(0.f, 0.f, 0.f, 0.f);
    float4 up1 = make_float4(0.f, 0.f, 0.f, 0.f);

    for (int t = 0; t < TT; t++) {
        const int m   = t & 1;
        const int par = (t >> 1) & 1;

        const float4 uc0 = un0, uc1 = un1;
        {   // prefetch next step's u
            int tn = (t + 1 < TT) ? (t + 1) : t;
            un0 = *(const float4*)&Ub[(size_t)tn * S + wcol];
            un1 = *(const float4*)&Ub[(size_t)tn * S + wcol + 4];
        }

        // h pairs (ulonglong2 = LDS.128)
        ull hp[4][2];
#pragma unroll
        for (int r = 0; r < 4; r++) {
            ulonglong2 hv = *(const ulonglong2*)&h_sm[4 * lane + 128 * r];
            hp[r][0] = hv.x; hp[r][1] = hv.y;
        }

        ull accA[8], accK[8];
#pragma unroll
        for (int c = 0; c < 8; c++) { accA[c] = 0ull; accK[c] = 0ull; }
#pragma unroll
        for (int c = 0; c < 8; c++) {
            const float* Ac = A_sm + (size_t)(8 * w + c) * S;
#pragma unroll
            for (int r = 0; r < 4; r++) {
                ulonglong2 av = *(const ulonglong2*)&Ac[4 * lane + 128 * r];
                accA[c] = ffma2(av.x, hp[r][0], accA[c]);
                accA[c] = ffma2(av.y, hp[r][1], accA[c]);
                accK[c] = ffma2(kp[c][r][0], hp[r][0], accK[c]);
                accK[c] = ffma2(kp[c][r][1], hp[r][1], accK[c]);
            }
        }
        float z[8];
        const float upv[8] = {up0.x, up0.y, up0.z, up0.w, up1.x, up1.y, up1.z, up1.w};
        const float ucv[8] = {uc0.x, uc0.y, uc0.z, uc0.w, uc1.x, uc1.y, uc1.z, uc1.w};
#pragma unroll
        for (int c = 0; c < 8; c++) {
            float2 a = upk(accA[c]), k = upk(accK[c]);
            z[c] = (a.x + a.y) + (k.x + k.y) * upv[c];
        }
#pragma unroll
        for (int off = 16; off > 0; off >>= 1) {
#pragma unroll
            for (int c = 0; c < 8; c++)
                z[c] += __shfl_xor_sync(0xffffffffu, z[c], off);
        }
        float s1 = 0.f, s2 = 0.f;
#pragma unroll
        for (int c = 0; c < 8; c++) {
            z[c] += abv[c] + ucv[c];
            s1 += z[c];
            s2 += z[c] * z[c];
        }

        // ---- broadcast: lane L -> rank L, st.async with remote tx accounting
        if (lane < 8) {
            const uint32_t mb = mdst + (uint32_t)(m * 8);
            uint32_t zd = zdst + (uint32_t)((m * S + wcol) * 4);
            st_async_b64(zd +  0, pk(z[0], z[1]), mb);
            st_async_b64(zd +  8, pk(z[2], z[3]), mb);
            st_async_b64(zd + 16, pk(z[4], z[5]), mb);
            st_async_b64(zd + 24, pk(z[6], z[7]), mb);
            st_async_b64(pdst + (uint32_t)((m * 64 + rank * 8 + w) * 8),
                         pk(s1, s2), mb);
        }
        up0 = uc0; up1 = uc1;

        // ---- consume
        mbar_wait_parity(mbar_u + m * 8, (uint32_t)par);
        if (tid == 0) mbar_expect_tx(mbar_u + m * 8, STEP_TX_BYTES);  // re-arm t+2

        // per-warp redundant LN-sum reduction over 64 (s1,s2) partials
        float4 pp = *(const float4*)&part[m * 128 + lane * 4];
        float t1 = pp.x + pp.z, t2 = pp.y + pp.w;
#pragma unroll
        for (int off = 16; off > 0; off >>= 1) {
            t1 += __shfl_xor_sync(0xffffffffu, t1, off);
            t2 += __shfl_xor_sync(0xffffffffu, t2, off);
        }
        const float mu   = t1 * (1.f / S);
        const float rinv = rsqrtf(t2 * (1.f / S) - mu * mu + LN_EPS);

        float2 zv = *(const float2*)&zb[m * S + 2 * tid];
        float zn0 = (zv.x - mu) * rinv * g2.x + b2.x;
        float zn1 = (zv.y - mu) * rinv * g2.y + b2.y;
        hreg.x += 0.5f * zn0 * (1.f + erff(zn0 * 0.70710678118654752f));
        hreg.y += 0.5f * zn1 * (1.f + erff(zn1 * 0.70710678118654752f));
        *(float2*)&h_sm[2 * tid] = hreg;
        if (rank == 0) *(float2*)&Hb[(size_t)t * S + 2 * tid] = hreg;
        __syncthreads();   // h_sm complete before next step's matmul
    }
    cluster_barrier();     // no CTA exits while peers may still touch its smem
}

// ---------------- fp32 tiled GEMM with packed f32x2 FMAs ----------------------
// C[M,N] = A[M,K] * B[K,N], all row-major. 128x128 tile, BK=16, 256 threads,
// 8x8 microtile. Inner loop: 32 FFMA2 + 8 packs + 4 LDS.128 per kk (was 64
// FFMA + 4 LDS) -> ~1.5x fewer issue slots, bit-identical numerics.
#define BM 128
#define BN 128
#define BK 16

__global__ void __launch_bounds__(256, 2)
gemm_kernel(const float* __restrict__ A, const float* __restrict__ B,
            float* __restrict__ C, int M, int N, int Kd)
{
    __shared__ float As[BK][BM];
    __shared__ float Bs[BK][BN];

    const int t  = threadIdx.x;
    const int tx = t & 15, ty = t >> 4;
    const int m0 = blockIdx.y * BM, n0 = blockIdx.x * BN;

    ull acc2[8][4];
#pragma unroll
    for (int i = 0; i < 8; i++)
#pragma unroll
        for (int j = 0; j < 4; j++) acc2[i][j] = 0ull;

    for (int k0 = 0; k0 < Kd; k0 += BK) {
#pragma unroll
        for (int q = 0; q < 2; q++) {
            int idx = t + q * 256;
            int arow = idx >> 2, kc = (idx & 3) * 4;
            float4 v = *(const float4*)&A[(size_t)(m0 + arow) * Kd + k0 + kc];
            As[kc + 0][arow] = v.x; As[kc + 1][arow] = v.y;
            As[kc + 2][arow] = v.z; As[kc + 3][arow] = v.w;
        }
#pragma unroll
        for (int q = 0; q < 2; q++) {
            int idx = t + q * 256;
            int brow = idx >> 5, bc = (idx & 31) * 4;
            *(float4*)&Bs[brow][bc] = *(const float4*)&B[(size_t)(k0 + brow) * N + n0 + bc];
        }
        __syncthreads();
#pragma unroll
        for (int kk = 0; kk < BK; kk++) {
            // b pairs straight from LDS.128 (no repacking)
            ulonglong2 bq0 = *(const ulonglong2*)&Bs[kk][tx * 4];
            ulonglong2 bq1 = *(const ulonglong2*)&Bs[kk][tx * 4 + 64];
            ull bp[4] = {bq0.x, bq0.y, bq1.x, bq1.y};
            float4 a0 = *(const float4*)&As[kk][ty * 4];
            float4 a1 = *(const float4*)&As[kk][ty * 4 + 64];
            float av[8] = {a0.x, a0.y, a0.z, a0.w, a1.x, a1.y, a1.z, a1.w};
#pragma unroll
            for (int i = 0; i < 8; i++) {
                ull ad = pk(av[i], av[i]);      // duplicate a into both halves
#pragma unroll
                for (int j = 0; j < 4; j++)
                    acc2[i][j] = ffma2(ad, bp[j], acc2[i][j]);
            }
        }
        __syncthreads();
    }

#pragma unroll
    for (int i = 0; i < 8; i++) {
        int row = m0 + ((i < 4) ? (ty * 4 + i) : (64 + ty * 4 + (i - 4)));
        float2 c0 = upk(acc2[i][0]), c1 = upk(acc2[i][1]);
        float2 c2 = upk(acc2[i][2]), c3 = upk(acc2[i][3]);
        *(float4*)&C[(size_t)row * N + n0 + tx * 4]      = make_float4(c0.x, c0.y, c1.x, c1.y);
        *(float4*)&C[(size_t)row * N + n0 + 64 + tx * 4] = make_float4(c2.x, c2.y, c3.x, c3.y);
    }
}

// ---------------- launch ------------------------------------------------------
extern "C" void kernel_launch(void* const* d_in, const int* in_sizes, int n_in,
                              void* d_out, int out_size)
{
    (void)in_sizes; (void)n_in; (void)out_size;
    const float* x   = (const float*)d_in[0];
    const float* A0  = (const float*)d_in[1];
    const float* B0  = (const float*)d_in[2];
    const float* C0  = (const float*)d_in[3];
    const float* K0  = (const float*)d_in[4];
    const float* ab0 = (const float*)d_in[5];
    const float* g0  = (const float*)d_in[6];
    const float* bt0 = (const float*)d_in[7];
    const float* A1  = (const float*)d_in[8];
    const float* B1  = (const float*)d_in[9];
    const float* C1  = (const float*)d_in[10];
    const float* K1  = (const float*)d_in[11];
    const float* ab1 = (const float*)d_in[12];
    const float* g1  = (const float*)d_in[13];
    const float* bt1 = (const float*)d_in[14];
    float* out = (float*)d_out;

    float *U, *H, *W01;
    cudaGetSymbolAddress((void**)&U,   g_bufU);
    cudaGetSymbolAddress((void**)&H,   g_bufH);
    cudaGetSymbolAddress((void**)&W01, g_W01);

    cudaFuncSetAttribute(scan_kernel, cudaFuncAttributeMaxDynamicSharedMemorySize,
                         (int)SCAN_SMEM);

    const int M = NB * TT;                        // 32768
    dim3 gBig(S / BN, M / BM);                    // (4, 256)
    dim3 gSmall(S / BN, S / BM);                  // (4, 4)

    // W01 = C0 @ B1   (fuse the inter-layer GEMM pair: (hs@C0)@B1 = hs@(C0@B1))
    gemm_kernel<<<gSmall, 256>>>(C0, B1, W01, S, S, S);
    // U = x @ B0
    gemm_kernel<<<gBig, 256>>>(x, B0, U, M, S, S);
    // layer 0 scan -> H
    scan_kernel<<<NB * CLU, NTHR, SCAN_SMEM>>>(A0, K0, ab0, g0, bt0, U, H);
    // U = H @ W01
    gemm_kernel<<<gBig, 256>>>(H, W01, U, M, S, S);
    // layer 1 scan -> H
    scan_kernel<<<NB * CLU, NTHR, SCAN_SMEM>>>(A1, K1, ab1, g1, bt1, U, H);
    // out = H @ C1
    gemm_kernel<<<gBig, 256>>>(H, C1, out, M, S, S);
}